// round 6
// baseline (speedup 1.0000x reference)
#include <cuda_runtime.h>
#include <cuda_bf16.h>
#include <math.h>
#include <stdint.h>

// Problem constants
#define T_DIM   36
#define NPOLES  40
#define KDIM    160          // 4*N_POLES
#define PDIM    4096
#define PCOLS   64           // p columns per CTA
#define NCTA    128
#define NTHREADS 256         // 8 warps: 2 (m) x 4 (n)
#define MAXIT   100
#define LAM_C   0.1f
#define TOL_C   1e-4f

#define YCOLSTR 672          // bytes per column in y buffer (bank-friendly)

// ---- dynamic smem layout (bytes) ----
#define RED_OFF   0          // 8 floats (per-warp partials)
#define STOP_OFF  64
#define A_HI_OFF  2048       // 100 frags * 32 lanes * 16B = 51200
#define A_LO_OFF  53248      // 51200
#define DTY_OFF   104448     // 80 c-frags * 32 * 16B = 40960
#define Y_OFF     145408     // 64 cols * 672B = 43008  (bf16 hi/lo pairs)
#define SMEM_TOTAL 188416
// startup staging (consumed before overwrite):
#define DICT_STAGE Y_OFF     // dict [36][160] fp32 = 23040 (< 43008)
#define X_STAGE    DTY_OFF   // x tile [36][64] fp32 = 9216

// ---------------- device globals ----------------
__device__ float    g_Dmat[T_DIM * KDIM];   // [t][k]
__device__ float    g_A[KDIM * KDIM];       // I - DtD/L  [k][j]
__device__ float    g_lambd;
__device__ float    g_linv;
__device__ float    g_tts[MAXIT];
__device__ float    g_part[NCTA];
__device__ unsigned g_count;
__device__ unsigned g_gen;                  // monotonic: # completed iterations

// ---------------- helpers ----------------
__device__ __forceinline__ void mma_bf16(float* c, const uint32_t* a, const uint32_t* b) {
    asm volatile(
        "mma.sync.aligned.m16n8k16.row.col.f32.bf16.bf16.f32 "
        "{%0,%1,%2,%3}, {%4,%5,%6,%7}, {%8,%9}, {%0,%1,%2,%3};"
        : "+f"(c[0]), "+f"(c[1]), "+f"(c[2]), "+f"(c[3])
        : "r"(a[0]), "r"(a[1]), "r"(a[2]), "r"(a[3]), "r"(b[0]), "r"(b[1]));
}
// pack (v0 -> low16, v1 -> high16) bf16 hi + residual lo
__device__ __forceinline__ void split_pack(float v0, float v1, uint32_t& hi, uint32_t& lo) {
    asm("cvt.rn.bf16x2.f32 %0, %1, %2;" : "=r"(hi) : "f"(v1), "f"(v0));
    float h0 = __uint_as_float(hi << 16);
    float h1 = __uint_as_float(hi & 0xffff0000u);
    asm("cvt.rn.bf16x2.f32 %0, %1, %2;" : "=r"(lo) : "f"(v1 - h1), "f"(v0 - h0));
}
// deterministic butterfly sum (identical instruction sequence everywhere)
__device__ __forceinline__ float warp_sum(float v) {
    v += __shfl_xor_sync(0xFFFFFFFFu, v, 16);
    v += __shfl_xor_sync(0xFFFFFFFFu, v, 8);
    v += __shfl_xor_sync(0xFFFFFFFFu, v, 4);
    v += __shfl_xor_sync(0xFFFFFFFFu, v, 2);
    v += __shfl_xor_sync(0xFFFFFFFFu, v, 1);
    return v;
}

// ---------------- setup ----------------
__global__ void setup_kernel(const float* __restrict__ Drr,
                             const float* __restrict__ Dtheta) {
    __shared__ float rbuf[256];
    __shared__ float s_linv;
    const int tid = threadIdx.x;

    if (tid < KDIM) {
        const int j = tid;
        const int g = j / NPOLES;
        const int n = j % NPOLES;
        const float rr = Drr[n];
        const float th = Dtheta[n];
        float vals[T_DIM];
        float pr = 1.0f, n2 = 0.0f;
        for (int i = 0; i < T_DIM; ++i) {
            float ang  = (float)i * th;
            float base = (g < 2) ? cosf(ang) : sinf(ang);
            float v = pr * base;
            if ((g & 1) && (i & 1)) v = -v;
            vals[i] = v; n2 += v * v; pr *= rr;
        }
        float G  = (n2 == 0.0f) ? 6.0f : sqrtf(n2);
        float gi = 1.0f / G;
        for (int i = 0; i < T_DIM; ++i) g_Dmat[i * KDIM + j] = vals[i] * gi;
    }
    __syncthreads();

    float sq = 0.0f;
    for (int e = tid; e < KDIM * KDIM; e += 256) {
        int i = e / KDIM, jj = e % KDIM;
        float s = 0.0f;
        for (int t = 0; t < T_DIM; ++t)
            s += g_Dmat[t * KDIM + i] * g_Dmat[t * KDIM + jj];
        g_A[e] = s;
        sq += s * s;
    }
    rbuf[tid] = sq;
    __syncthreads();
    if (tid == 0) {
        float tot = 0.0f;
        for (int i = 0; i < 256; ++i) tot += rbuf[i];
        float L = sqrtf(tot);
        s_linv  = 1.0f / L;
        g_linv  = s_linv;
        g_lambd = LAM_C * s_linv;
        double t = 1.0;
        for (int k = 0; k < MAXIT; ++k) {
            double tn = (1.0 + sqrt(1.0 + 4.0 * t * t)) * 0.5;
            g_tts[k] = (float)((t - 1.0) / tn);
            t = tn;
        }
        g_count = 0;
        g_gen   = 0;
    }
    __syncthreads();
    const float linv = s_linv;
    for (int e = tid; e < KDIM * KDIM; e += 256) {
        int i = e / KDIM, jj = e % KDIM;
        g_A[e] = ((i == jj) ? 1.0f : 0.0f) - g_A[e] * linv;
    }
    if (tid < NCTA) g_part[tid] = 0.0f;
}

// ---------------- persistent FISTA kernel (mma.sync bf16, permuted-k y) ----
__global__ void __launch_bounds__(NTHREADS, 1)
fista_kernel(const float* __restrict__ x_in, float* __restrict__ out) {
    extern __shared__ __align__(16) char smem[];
    float* red    = (float*)(smem + RED_OFF);
    int*   s_stop = (int*)(smem + STOP_OFF);

    const int tid = threadIdx.x;
    const int wid = tid >> 5;
    const int l   = tid & 31;
    const int wm  = wid >> 2;          // 0..1  (80-row half)
    const int wn  = wid & 3;           // 0..3  (16-col stripe)
    const int g   = l >> 2;            // groupID
    const int i4  = l & 3;             // threadID_in_group
    const int cta = blockIdx.x;
    const int b   = cta >> 6;
    const int p0  = (cta & 63) * PCOLS;

    const float linv  = g_linv;
    const float lambd = g_lambd;

    // ---- stage dict [36][160] and x tile [36][64] fp32 ----
    for (int e = tid; e < T_DIM * KDIM; e += NTHREADS)
        *(float*)(smem + DICT_STAGE + e * 4) = g_Dmat[e];
    for (int e = tid; e < T_DIM * PCOLS; e += NTHREADS) {
        int t = e >> 6, pp = e & 63;
        *(float*)(smem + X_STAGE + e * 4) = x_in[(b * T_DIM + t) * PDIM + p0 + pp];
    }
    __syncthreads();

    // ---- DtY = linv * D^T x -> registers (c-frag order per thread) ----
    float dty[40];
    {
        #pragma unroll
        for (int v = 0; v < 40; ++v) dty[v] = 0.0f;
        const float* Ds = (const float*)(smem + DICT_STAGE);
        const float* Xs = (const float*)(smem + X_STAGE);
        for (int t = 0; t < T_DIM; ++t) {
            float dr[10], xc[4];
            #pragma unroll
            for (int mt = 0; mt < 5; ++mt) {
                dr[mt * 2]     = Ds[t * KDIM + wm * 80 + mt * 16 + g];
                dr[mt * 2 + 1] = Ds[t * KDIM + wm * 80 + mt * 16 + g + 8];
            }
            #pragma unroll
            for (int nt = 0; nt < 2; ++nt) {
                xc[nt * 2]     = Xs[t * PCOLS + wn * 16 + nt * 8 + i4 * 2];
                xc[nt * 2 + 1] = Xs[t * PCOLS + wn * 16 + nt * 8 + i4 * 2 + 1];
            }
            #pragma unroll
            for (int mt = 0; mt < 5; ++mt)
                #pragma unroll
                for (int nt = 0; nt < 2; ++nt)
                    #pragma unroll
                    for (int q = 0; q < 4; ++q)
                        dty[(mt * 2 + nt) * 4 + q] =
                            fmaf(dr[mt * 2 + (q >> 1)], xc[nt * 2 + (q & 1)],
                                 dty[(mt * 2 + nt) * 4 + q]);
        }
        #pragma unroll
        for (int v = 0; v < 40; ++v) dty[v] *= linv;
    }
    __syncthreads();   // dict/x staging consumed

    // ---- pack A into fragment-native bf16 hi/lo layout, k-PERMUTED ----
    // slot s within a k16 block holds original k(s) = (s>>1) + 8*(s&1).
    // reg r covers slots s0 = 2*i4 + ((r&2)?8:0), s0+1:
    //   v0 = A[row][ks*16 + i4 + ((r&2)?4:0)], v1 = same + 8.
    for (int e = tid; e < 100 * 32 * 4; e += NTHREADS) {
        int frag = e >> 7;
        int lane = (e >> 2) & 31;
        int reg  = e & 3;
        int mt   = frag / 10, ks = frag % 10;
        int r = mt * 16 + (lane >> 2) + ((reg & 1) ? 8 : 0);
        int kbase = ks * 16 + (lane & 3) + ((reg & 2) ? 4 : 0);
        float v0 = g_A[r * KDIM + kbase];
        float v1 = g_A[r * KDIM + kbase + 8];
        uint32_t hi, lo;
        split_pack(v0, v1, hi, lo);
        *(uint32_t*)(smem + A_HI_OFF + e * 4) = hi;
        *(uint32_t*)(smem + A_LO_OFF + e * 4) = lo;
    }
    // ---- store DtY packed (c-frag layout) ----
    #pragma unroll
    for (int mt = 0; mt < 5; ++mt)
        #pragma unroll
        for (int nt = 0; nt < 2; ++nt) {
            int fragc = (wm * 5 + mt) * 8 + (wn * 2 + nt);
            *(float4*)(smem + DTY_OFF + (fragc * 32 + l) * 16) =
                make_float4(dty[(mt * 2 + nt) * 4 + 0], dty[(mt * 2 + nt) * 4 + 1],
                            dty[(mt * 2 + nt) * 4 + 2], dty[(mt * 2 + nt) * 4 + 3]);
        }
    // ---- zero y (bf16 hi/lo pair buffer) ----
    for (int e = tid; e < (PCOLS * YCOLSTR) / 16; e += NTHREADS)
        ((uint4*)(smem + Y_OFF))[e] = make_uint4(0, 0, 0, 0);

    float xold[40];
    #pragma unroll
    for (int v = 0; v < 40; ++v) xold[v] = 0.0f;
    __syncthreads();

    // ---- main FISTA loop (barrier hidden behind next GEMM) ----
    for (int it = 0; it < MAXIT; ++it) {
        // init acc with DtY
        float acc[10][4];
        #pragma unroll
        for (int mt = 0; mt < 5; ++mt)
            #pragma unroll
            for (int nt = 0; nt < 2; ++nt) {
                int fragc = (wm * 5 + mt) * 8 + (wn * 2 + nt);
                float4 c = *(const float4*)(smem + DTY_OFF + (fragc * 32 + l) * 16);
                acc[mt * 2 + nt][0] = c.x; acc[mt * 2 + nt][1] = c.y;
                acc[mt * 2 + nt][2] = c.z; acc[mt * 2 + nt][3] = c.w;
            }

        // GEMM: D[k,p] += A @ y (3-chain split bf16); y already bf16 hi/lo
        // in fragment-pair layout: pair p of column c at Y + c*672 + p*8.
        #pragma unroll 2
        for (int ks = 0; ks < 10; ++ks) {
            uint32_t bh[2][2], bl[2][2];
            #pragma unroll
            for (int nt = 0; nt < 2; ++nt) {
                const char* ybase = smem + Y_OFF
                    + (wn * 16 + nt * 8 + g) * YCOLSTR + (ks * 8 + i4) * 8;
                uint2 u0 = *(const uint2*)(ybase);        // pair i4   (b0)
                uint2 u1 = *(const uint2*)(ybase + 32);   // pair i4+4 (b1)
                bh[nt][0] = u0.x; bl[nt][0] = u0.y;
                bh[nt][1] = u1.x; bl[nt][1] = u1.y;
            }
            uint32_t ah[5][4], al[5][4];
            #pragma unroll
            for (int mt = 0; mt < 5; ++mt) {
                int fi = ((wm * 5 + mt) * 10 + ks) * 32 + l;
                uint4 Ah = *(const uint4*)(smem + A_HI_OFF + fi * 16);
                uint4 Al = *(const uint4*)(smem + A_LO_OFF + fi * 16);
                ah[mt][0] = Ah.x; ah[mt][1] = Ah.y; ah[mt][2] = Ah.z; ah[mt][3] = Ah.w;
                al[mt][0] = Al.x; al[mt][1] = Al.y; al[mt][2] = Al.z; al[mt][3] = Al.w;
            }
            #pragma unroll
            for (int mt = 0; mt < 5; ++mt)
                #pragma unroll
                for (int nt = 0; nt < 2; ++nt)
                    mma_bf16(acc[mt * 2 + nt], ah[mt], bh[nt]);
            #pragma unroll
            for (int mt = 0; mt < 5; ++mt)
                #pragma unroll
                for (int nt = 0; nt < 2; ++nt)
                    mma_bf16(acc[mt * 2 + nt], ah[mt], bl[nt]);
            #pragma unroll
            for (int mt = 0; mt < 5; ++mt)
                #pragma unroll
                for (int nt = 0; nt < 2; ++nt)
                    mma_bf16(acc[mt * 2 + nt], al[mt], bh[nt]);
        }

        // ---- resolve stop decision for iteration it-1 (overlapped) ----
        if (it > 0) {
            if (tid == 0) {
                while (*((volatile unsigned*)&g_gen) < (unsigned)it) { __nanosleep(32); }
            }
        }
        __syncthreads();   // joins poll; all warps done reading y
        if (it > 0) {
            if (wid == 0) {
                float s = *((volatile float*)(g_part + l));
                s += *((volatile float*)(g_part + l + 32));
                s += *((volatile float*)(g_part + l + 64));
                s += *((volatile float*)(g_part + l + 96));
                float tot = warp_sum(s);
                if (l == 0) {
                    float denom = (it == 1) ? (float)PDIM : (float)KDIM;
                    *s_stop = (sqrtf(tot) < TOL_C * denom) ? 1 : 0;
                }
            }
            __syncthreads();
            if (*s_stop) break;   // xold holds x_it (frozen), matches reference
        }

        const float tt = g_tts[it];
        float dsum = 0.0f;

        // epilogue: shrink + momentum + ||dx||^2 + pack y bf16 hi/lo
        #pragma unroll
        for (int mt = 0; mt < 5; ++mt)
            #pragma unroll
            for (int nt = 0; nt < 2; ++nt) {
                float yn[4];
                #pragma unroll
                for (int q = 0; q < 4; ++q) {
                    int ix = (mt * 2 + nt) * 4 + q;
                    float v  = acc[mt * 2 + nt][q];
                    float a  = fabsf(v) - lambd;
                    float xn = (a > 0.0f) ? copysignf(a, v) : 0.0f;
                    float xo = xold[ix];
                    float d  = xn - xo;
                    dsum = fmaf(d, d, dsum);
                    yn[q] = fmaf(tt, d, xn);   // xn*(1+tt) - xo*tt
                    xold[ix] = xn;
                }
                // pack per column eps: rows (g, g+8) -> slot pair (2g, 2g+1)
                const int pairIdx = wm * 40 + mt * 8 + g;
                #pragma unroll
                for (int eps = 0; eps < 2; ++eps) {
                    uint32_t hi, lo;
                    split_pack(yn[eps], yn[2 + eps], hi, lo);
                    int col = wn * 16 + nt * 8 + i4 * 2 + eps;
                    *(uint2*)(smem + Y_OFF + col * YCOLSTR + pairIdx * 8) =
                        make_uint2(hi, lo);
                }
            }

        // deterministic block reduce: warp butterfly + 8-way serial (fixed order)
        float ws = warp_sum(dsum);
        if (l == 0) red[wid] = ws;
        __syncthreads();   // also: y writes visible before next GEMM
        if (tid == 0) {
            float s = red[0];
            #pragma unroll
            for (int i = 1; i < 8; ++i) s += red[i];
            g_part[cta] = s;
            __threadfence();
            unsigned tk = atomicAdd(&g_count, 1);
            if (tk == (unsigned)(NCTA - 1)) {
                g_count = 0;
                __threadfence();
                atomicAdd(&g_gen, 1);   // completed iteration count
            }
        }
        // NO wait here — next GEMM starts immediately; decision deferred.
    }

    // ---- output: out[(b*160 + row)*4096 + p0 + col] ----
    #pragma unroll
    for (int mt = 0; mt < 5; ++mt)
        #pragma unroll
        for (int nt = 0; nt < 2; ++nt)
            #pragma unroll
            for (int q = 0; q < 4; ++q) {
                int row = wm * 80 + mt * 16 + g + ((q >> 1) << 3);
                int col = wn * 16 + nt * 8 + i4 * 2 + (q & 1);
                out[((size_t)b * KDIM + row) * PDIM + p0 + col] =
                    xold[(mt * 2 + nt) * 4 + q];
            }
}

// ---------------- launch ----------------
extern "C" void kernel_launch(void* const* d_in, const int* in_sizes, int n_in,
                              void* d_out, int out_size) {
    const float* Drr    = (const float*)d_in[0];
    const float* Dtheta = (const float*)d_in[1];
    const float* x      = (const float*)d_in[2];
    float* out = (float*)d_out;

    cudaFuncSetAttribute(fista_kernel, cudaFuncAttributeMaxDynamicSharedMemorySize, SMEM_TOTAL);
    setup_kernel<<<1, 256>>>(Drr, Dtheta);
    fista_kernel<<<NCTA, NTHREADS, SMEM_TOTAL>>>(x, out);
}

// round 9
// speedup vs baseline: 1.1543x; 1.1543x over previous
#include <cuda_runtime.h>
#include <cuda_bf16.h>
#include <math.h>
#include <stdint.h>

// Problem constants
#define T_DIM   36
#define NPOLES  40
#define KDIM    160          // 4*N_POLES
#define PDIM    4096
#define PCOLS   64           // p columns per CTA
#define NCTA    128
#define NTHREADS 256         // 8 warps: 2 (m) x 4 (n)
#define MAXIT   100
#define LAM_C   0.1f
#define TOL_C   1e-4f

#define YSTR    164          // y fp32 column stride (words); even -> float2 aligned,
                             // conflict-free loads (4g+2i4 overlaps are broadcasts)
                             // and stores (8*i4+g distinct banks)

// ---- dynamic smem layout (bytes) ----
#define RED_OFF   0          // 8 floats (per-warp partials)
#define STOP_OFF  64
#define TTS_OFF   128        // 100 floats
#define A_HI_OFF  1024       // 100 frags * 32 lanes * 16B = 51200
#define A_LO_OFF  52224      // 51200
#define Y_OFF     103424     // 64 cols * 164 * 4 = 41984
#define SMEM_TOTAL 145408
// startup staging (inside Y region, consumed before y zeroing):
#define DICT_STAGE Y_OFF            // dict [36][160] fp32 = 23040
#define X_STAGE   (Y_OFF + 23040)   // x tile [36][64] fp32 = 9216

// ---------------- device globals ----------------
__device__ float    g_Dmat[T_DIM * KDIM];   // [t][k]
__device__ float    g_A[KDIM * KDIM];       // I - DtD/L  [k][j]
__device__ float    g_lambd;
__device__ float    g_linv;
__device__ float    g_tts[MAXIT];
__device__ float    g_part[NCTA];
__device__ unsigned g_count;
__device__ unsigned g_gen;                  // monotonic: # completed iterations

// ---------------- helpers ----------------
__device__ __forceinline__ void mma_bf16(float* c, const uint32_t* a, const uint32_t* b) {
    asm volatile(
        "mma.sync.aligned.m16n8k16.row.col.f32.bf16.bf16.f32 "
        "{%0,%1,%2,%3}, {%4,%5,%6,%7}, {%8,%9}, {%0,%1,%2,%3};"
        : "+f"(c[0]), "+f"(c[1]), "+f"(c[2]), "+f"(c[3])
        : "r"(a[0]), "r"(a[1]), "r"(a[2]), "r"(a[3]), "r"(b[0]), "r"(b[1]));
}
__device__ __forceinline__ void split_pack(float v0, float v1, uint32_t& hi, uint32_t& lo) {
    asm("cvt.rn.bf16x2.f32 %0, %1, %2;" : "=r"(hi) : "f"(v1), "f"(v0));
    float h0 = __uint_as_float(hi << 16);
    float h1 = __uint_as_float(hi & 0xffff0000u);
    asm("cvt.rn.bf16x2.f32 %0, %1, %2;" : "=r"(lo) : "f"(v1 - h1), "f"(v0 - h0));
}
// deterministic butterfly sum (identical instruction sequence everywhere)
__device__ __forceinline__ float warp_sum(float v) {
    v += __shfl_xor_sync(0xFFFFFFFFu, v, 16);
    v += __shfl_xor_sync(0xFFFFFFFFu, v, 8);
    v += __shfl_xor_sync(0xFFFFFFFFu, v, 4);
    v += __shfl_xor_sync(0xFFFFFFFFu, v, 2);
    v += __shfl_xor_sync(0xFFFFFFFFu, v, 1);
    return v;
}

// ---------------- setup ----------------
__global__ void setup_kernel(const float* __restrict__ Drr,
                             const float* __restrict__ Dtheta) {
    __shared__ float rbuf[256];
    __shared__ float s_linv;
    const int tid = threadIdx.x;

    if (tid < KDIM) {
        const int j = tid;
        const int g = j / NPOLES;
        const int n = j % NPOLES;
        const float rr = Drr[n];
        const float th = Dtheta[n];
        float vals[T_DIM];
        float pr = 1.0f, n2 = 0.0f;
        for (int i = 0; i < T_DIM; ++i) {
            float ang  = (float)i * th;
            float base = (g < 2) ? cosf(ang) : sinf(ang);
            float v = pr * base;
            if ((g & 1) && (i & 1)) v = -v;
            vals[i] = v; n2 += v * v; pr *= rr;
        }
        float G  = (n2 == 0.0f) ? 6.0f : sqrtf(n2);
        float gi = 1.0f / G;
        for (int i = 0; i < T_DIM; ++i) g_Dmat[i * KDIM + j] = vals[i] * gi;
    }
    __syncthreads();

    float sq = 0.0f;
    for (int e = tid; e < KDIM * KDIM; e += 256) {
        int i = e / KDIM, jj = e % KDIM;
        float s = 0.0f;
        for (int t = 0; t < T_DIM; ++t)
            s += g_Dmat[t * KDIM + i] * g_Dmat[t * KDIM + jj];
        g_A[e] = s;
        sq += s * s;
    }
    rbuf[tid] = sq;
    __syncthreads();
    if (tid == 0) {
        float tot = 0.0f;
        for (int i = 0; i < 256; ++i) tot += rbuf[i];
        float L = sqrtf(tot);
        s_linv  = 1.0f / L;
        g_linv  = s_linv;
        g_lambd = LAM_C * s_linv;
        double t = 1.0;
        for (int k = 0; k < MAXIT; ++k) {
            double tn = (1.0 + sqrt(1.0 + 4.0 * t * t)) * 0.5;
            g_tts[k] = (float)((t - 1.0) / tn);
            t = tn;
        }
        g_count = 0;
        g_gen   = 0;
    }
    __syncthreads();
    const float linv = s_linv;
    for (int e = tid; e < KDIM * KDIM; e += 256) {
        int i = e / KDIM, jj = e % KDIM;
        g_A[e] = ((i == jj) ? 1.0f : 0.0f) - g_A[e] * linv;
    }
    if (tid < NCTA) g_part[tid] = 0.0f;
}

// ---------------- persistent FISTA kernel (mma.sync bf16) ----------------
__global__ void __launch_bounds__(NTHREADS, 1)
fista_kernel(const float* __restrict__ x_in, float* __restrict__ out) {
    extern __shared__ __align__(16) char smem[];
    float* red    = (float*)(smem + RED_OFF);
    int*   s_stop = (int*)(smem + STOP_OFF);
    float* tts_s  = (float*)(smem + TTS_OFF);

    const int tid = threadIdx.x;
    const int wid = tid >> 5;
    const int l   = tid & 31;
    const int wm  = wid >> 2;          // 0..1  (80-row half)
    const int wn  = wid & 3;           // 0..3  (16-col stripe)
    const int g   = l >> 2;            // groupID
    const int i4  = l & 3;             // threadID_in_group
    const int cta = blockIdx.x;
    const int b   = cta >> 6;
    const int p0  = (cta & 63) * PCOLS;

    const float linv  = g_linv;
    const float lambd = g_lambd;

    // ---- stage dict [36][160] and x tile [36][64] fp32; copy tts ----
    for (int e = tid; e < T_DIM * KDIM; e += NTHREADS)
        *(float*)(smem + DICT_STAGE + e * 4) = g_Dmat[e];
    for (int e = tid; e < T_DIM * PCOLS; e += NTHREADS) {
        int t = e >> 6, pp = e & 63;
        *(float*)(smem + X_STAGE + e * 4) = x_in[(b * T_DIM + t) * PDIM + p0 + pp];
    }
    if (tid < MAXIT) tts_s[tid] = g_tts[tid];
    __syncthreads();

    // ---- DtY = linv * D^T x -> registers (c-frag order), KEPT IN REGS ----
    float dty[40];
    {
        #pragma unroll
        for (int v = 0; v < 40; ++v) dty[v] = 0.0f;
        const float* Ds = (const float*)(smem + DICT_STAGE);
        const float* Xs = (const float*)(smem + X_STAGE);
        for (int t = 0; t < T_DIM; ++t) {
            float dr[10], xc[4];
            #pragma unroll
            for (int mt = 0; mt < 5; ++mt) {
                dr[mt * 2]     = Ds[t * KDIM + wm * 80 + mt * 16 + g];
                dr[mt * 2 + 1] = Ds[t * KDIM + wm * 80 + mt * 16 + g + 8];
            }
            #pragma unroll
            for (int nt = 0; nt < 2; ++nt) {
                xc[nt * 2]     = Xs[t * PCOLS + wn * 16 + nt * 8 + i4 * 2];
                xc[nt * 2 + 1] = Xs[t * PCOLS + wn * 16 + nt * 8 + i4 * 2 + 1];
            }
            #pragma unroll
            for (int mt = 0; mt < 5; ++mt)
                #pragma unroll
                for (int nt = 0; nt < 2; ++nt)
                    #pragma unroll
                    for (int q = 0; q < 4; ++q)
                        dty[(mt * 2 + nt) * 4 + q] =
                            fmaf(dr[mt * 2 + (q >> 1)], xc[nt * 2 + (q & 1)],
                                 dty[(mt * 2 + nt) * 4 + q]);
        }
        #pragma unroll
        for (int v = 0; v < 40; ++v) dty[v] *= linv;
    }
    __syncthreads();   // dict/x staging consumed

    // ---- pack A into fragment-native bf16 hi/lo layout ----
    for (int e = tid; e < 100 * 32 * 4; e += NTHREADS) {
        int frag = e >> 7;
        int lane = (e >> 2) & 31;
        int reg  = e & 3;
        int mt   = frag / 10, ks = frag % 10;
        int r = mt * 16 + (lane >> 2) + ((reg & 1) ? 8 : 0);
        int k = ks * 16 + (lane & 3) * 2 + ((reg & 2) ? 8 : 0);
        float v0 = g_A[r * KDIM + k];
        float v1 = g_A[r * KDIM + k + 1];
        uint32_t hi, lo;
        split_pack(v0, v1, hi, lo);
        *(uint32_t*)(smem + A_HI_OFF + e * 4) = hi;
        *(uint32_t*)(smem + A_LO_OFF + e * 4) = lo;
    }
    // ---- zero y (fp32) ----
    for (int e = tid; e < PCOLS * YSTR; e += NTHREADS)
        *(float*)(smem + Y_OFF + e * 4) = 0.0f;

    float xold[40];
    #pragma unroll
    for (int v = 0; v < 40; ++v) xold[v] = 0.0f;
    __syncthreads();

    const float* Yp = (const float*)(smem + Y_OFF);

    // ---- main FISTA loop ----
    // structure: GEMM -> sync_A (joins gen-poll) -> [w0: stop decision (overlapped)]
    //            epilogue -> sync_B -> stop? rollback+break : publish partial.
    for (int it = 0; it < MAXIT; ++it) {
        // init acc with DtY (registers)
        float acc[10][4];
        #pragma unroll
        for (int mt = 0; mt < 5; ++mt)
            #pragma unroll
            for (int nt = 0; nt < 2; ++nt)
                #pragma unroll
                for (int q = 0; q < 4; ++q)
                    acc[mt * 2 + nt][q] = dty[(mt * 2 + nt) * 4 + q];

        // GEMM: D[k,p] += A @ y (3-chain split bf16)
        #pragma unroll 2
        for (int ks = 0; ks < 10; ++ks) {
            uint32_t bh[2][2], bl[2][2];
            #pragma unroll
            for (int nt = 0; nt < 2; ++nt) {
                const float* yrow = Yp + (wn * 16 + nt * 8 + g) * YSTR + ks * 16 + i4 * 2;
                float2 v0 = *(const float2*)(yrow);
                float2 v1 = *(const float2*)(yrow + 8);
                split_pack(v0.x, v0.y, bh[nt][0], bl[nt][0]);
                split_pack(v1.x, v1.y, bh[nt][1], bl[nt][1]);
            }
            uint32_t ah[5][4], al[5][4];
            #pragma unroll
            for (int mt = 0; mt < 5; ++mt) {
                int fi = ((wm * 5 + mt) * 10 + ks) * 32 + l;
                uint4 Ah = *(const uint4*)(smem + A_HI_OFF + fi * 16);
                uint4 Al = *(const uint4*)(smem + A_LO_OFF + fi * 16);
                ah[mt][0] = Ah.x; ah[mt][1] = Ah.y; ah[mt][2] = Ah.z; ah[mt][3] = Ah.w;
                al[mt][0] = Al.x; al[mt][1] = Al.y; al[mt][2] = Al.z; al[mt][3] = Al.w;
            }
            #pragma unroll
            for (int mt = 0; mt < 5; ++mt)
                #pragma unroll
                for (int nt = 0; nt < 2; ++nt)
                    mma_bf16(acc[mt * 2 + nt], ah[mt], bh[nt]);
            #pragma unroll
            for (int mt = 0; mt < 5; ++mt)
                #pragma unroll
                for (int nt = 0; nt < 2; ++nt)
                    mma_bf16(acc[mt * 2 + nt], ah[mt], bl[nt]);
            #pragma unroll
            for (int mt = 0; mt < 5; ++mt)
                #pragma unroll
                for (int nt = 0; nt < 2; ++nt)
                    mma_bf16(acc[mt * 2 + nt], al[mt], bh[nt]);
        }

        // join the gen-poll (partials of it-1 globally visible after this)
        if (it > 0 && tid == 0) {
            while (*((volatile unsigned*)&g_gen) < (unsigned)it) { __nanosleep(32); }
        }
        __syncthreads();   // sync_A: y reads done; poll joined

        // stop decision for it-1, overlapped with epilogue (w0 only)
        if (it > 0 && wid == 0) {
            float s = *((volatile float*)(g_part + l));
            s += *((volatile float*)(g_part + l + 32));
            s += *((volatile float*)(g_part + l + 64));
            s += *((volatile float*)(g_part + l + 96));
            float tot = warp_sum(s);
            if (l == 0) {
                float denom = (it == 1) ? (float)PDIM : (float)KDIM;
                *s_stop = (sqrtf(tot) < TOL_C * denom) ? 1 : 0;
            }
        }

        const float tt = tts_s[it];
        float dsum = 0.0f;

        // epilogue (speculative): shrink + momentum + ||dx||^2 + write y fp32
        #pragma unroll
        for (int mt = 0; mt < 5; ++mt)
            #pragma unroll
            for (int nt = 0; nt < 2; ++nt)
                #pragma unroll
                for (int q = 0; q < 4; ++q) {
                    int ix = (mt * 2 + nt) * 4 + q;
                    float v  = acc[mt * 2 + nt][q];
                    float a  = fabsf(v) - lambd;
                    float xn = (a > 0.0f) ? copysignf(a, v) : 0.0f;
                    float xo = xold[ix];
                    float d  = xn - xo;
                    dsum = fmaf(d, d, dsum);
                    float yn = fmaf(tt, d, xn);
                    xold[ix] = xn;
                    int row = wm * 80 + mt * 16 + g + ((q >> 1) << 3);
                    int col = wn * 16 + nt * 8 + i4 * 2 + (q & 1);
                    *(float*)(smem + Y_OFF + (col * YSTR + row) * 4) = yn;
                }

        float ws = warp_sum(dsum);
        if (l == 0) red[wid] = ws;
        __syncthreads();   // sync_B: y + red + s_stop visible

        if (it > 0 && *s_stop) {
            // rollback: epilogue ran speculatively; recover x_it exactly:
            // y = xn + tt*(xn - xo)  =>  xo = xn - (y - xn)/tt   (tt > 0 for it>=1)
            float inv_tt = 1.0f / tt;
            #pragma unroll
            for (int mt = 0; mt < 5; ++mt)
                #pragma unroll
                for (int nt = 0; nt < 2; ++nt)
                    #pragma unroll
                    for (int q = 0; q < 4; ++q) {
                        int ix  = (mt * 2 + nt) * 4 + q;
                        int row = wm * 80 + mt * 16 + g + ((q >> 1) << 3);
                        int col = wn * 16 + nt * 8 + i4 * 2 + (q & 1);
                        float yv = *(const float*)(smem + Y_OFF + (col * YSTR + row) * 4);
                        float xn = xold[ix];
                        xold[ix] = xn - (yv - xn) * inv_tt;
                    }
            break;
        }

        // publish partial + arrive
        if (tid == 0) {
            float s = red[0];
            #pragma unroll
            for (int i = 1; i < 8; ++i) s += red[i];
            g_part[cta] = s;
            __threadfence();
            unsigned tk = atomicAdd(&g_count, 1);
            if (tk == (unsigned)(NCTA - 1)) {
                g_count = 0;
                __threadfence();
                atomicAdd(&g_gen, 1);
            }
        }
        // no wait — next GEMM starts immediately; decision deferred.
    }

    // ---- output: out[(b*160 + row)*4096 + p0 + col] ----
    #pragma unroll
    for (int mt = 0; mt < 5; ++mt)
        #pragma unroll
        for (int nt = 0; nt < 2; ++nt)
            #pragma unroll
            for (int q = 0; q < 4; ++q) {
                int row = wm * 80 + mt * 16 + g + ((q >> 1) << 3);
                int col = wn * 16 + nt * 8 + i4 * 2 + (q & 1);
                out[((size_t)b * KDIM + row) * PDIM + p0 + col] =
                    xold[(mt * 2 + nt) * 4 + q];
            }
}

// ---------------- launch ----------------
extern "C" void kernel_launch(void* const* d_in, const int* in_sizes, int n_in,
                              void* d_out, int out_size) {
    const float* Drr    = (const float*)d_in[0];
    const float* Dtheta = (const float*)d_in[1];
    const float* x      = (const float*)d_in[2];
    float* out = (float*)d_out;

    cudaFuncSetAttribute(fista_kernel, cudaFuncAttributeMaxDynamicSharedMemorySize, SMEM_TOTAL);
    setup_kernel<<<1, 256>>>(Drr, Dtheta);
    fista_kernel<<<NCTA, NTHREADS, SMEM_TOTAL>>>(x, out);
}

// round 10
// speedup vs baseline: 1.2420x; 1.0760x over previous
#include <cuda_runtime.h>
#include <cuda_bf16.h>
#include <math.h>
#include <stdint.h>

// Problem constants
#define T_DIM   36
#define NPOLES  40
#define KDIM    160          // 4*N_POLES
#define PDIM    4096
#define PCOLS   64           // p columns per CTA
#define NCTA    128
#define NTHREADS 256         // 8 warps: stage1 = 8 n-stripes; stage2 = 2(m) x 4(n)
#define MAXIT   100
#define LAM_C   0.1f
#define TOL_C   1e-4f

#define YSTR    164          // y fp32 column stride (words); proven conflict pattern
#define ZSTR    68           // z fp32 column stride; 68 ≡ 164 (mod 32) -> same banks

// ---- dynamic smem layout (bytes) ----
#define RED_OFF   0          // 8 floats (per-warp partials)
#define STOP_OFF  64
#define TTS_OFF   128        // 100 floats
#define A1H_OFF   1024                  // D48 frags   : 30*512 = 15360
#define A1L_OFF   (A1H_OFF + 15360)
#define A2H_OFF   (A1L_OFF + 15360)     // -linv*D^T frags
#define A2L_OFF   (A2H_OFF + 15360)
#define Y_OFF     (A2L_OFF + 15360)     // 62464; 64 cols * 164 * 4 = 41984
#define Z_OFF     (Y_OFF + 41984)       // 104448; 64 cols * 68 * 4 = 17408
#define SMEM_TOTAL (Z_OFF + 17408)      // 121856
// startup staging (inside Y region, consumed before y zeroing):
#define DICT_STAGE Y_OFF                // dict [36][160] fp32 = 23040
#define X_STAGE   (Y_OFF + 23040)       // x tile [36][64] fp32 = 9216

// ---------------- device globals ----------------
__device__ float    g_Dmat[T_DIM * KDIM];   // [t][k] normalized dictionary
__device__ float    g_lambd;
__device__ float    g_linv;
__device__ float    g_tts[MAXIT];
__device__ float    g_part[NCTA];
__device__ unsigned g_count;
__device__ unsigned g_gen;                  // monotonic: # completed iterations

// ---------------- helpers ----------------
__device__ __forceinline__ void mma_bf16(float* c, const uint32_t* a, const uint32_t* b) {
    asm volatile(
        "mma.sync.aligned.m16n8k16.row.col.f32.bf16.bf16.f32 "
        "{%0,%1,%2,%3}, {%4,%5,%6,%7}, {%8,%9}, {%0,%1,%2,%3};"
        : "+f"(c[0]), "+f"(c[1]), "+f"(c[2]), "+f"(c[3])
        : "r"(a[0]), "r"(a[1]), "r"(a[2]), "r"(a[3]), "r"(b[0]), "r"(b[1]));
}
__device__ __forceinline__ void split_pack(float v0, float v1, uint32_t& hi, uint32_t& lo) {
    asm("cvt.rn.bf16x2.f32 %0, %1, %2;" : "=r"(hi) : "f"(v1), "f"(v0));
    float h0 = __uint_as_float(hi << 16);
    float h1 = __uint_as_float(hi & 0xffff0000u);
    asm("cvt.rn.bf16x2.f32 %0, %1, %2;" : "=r"(lo) : "f"(v1 - h1), "f"(v0 - h0));
}
__device__ __forceinline__ float warp_sum(float v) {
    v += __shfl_xor_sync(0xFFFFFFFFu, v, 16);
    v += __shfl_xor_sync(0xFFFFFFFFu, v, 8);
    v += __shfl_xor_sync(0xFFFFFFFFu, v, 4);
    v += __shfl_xor_sync(0xFFFFFFFFu, v, 2);
    v += __shfl_xor_sync(0xFFFFFFFFu, v, 1);
    return v;
}

// ---------------- setup (1024 threads; no explicit A matrix) ----------------
__global__ void setup_kernel(const float* __restrict__ Drr,
                             const float* __restrict__ Dtheta) {
    __shared__ float rbuf[32];
    const int tid = threadIdx.x;

    // 1. normalized dictionary
    if (tid < KDIM) {
        const int j = tid;
        const int g = j / NPOLES;
        const int n = j % NPOLES;
        const float rr = Drr[n];
        const float th = Dtheta[n];
        float vals[T_DIM];
        float pr = 1.0f, n2 = 0.0f;
        for (int i = 0; i < T_DIM; ++i) {
            float ang  = (float)i * th;
            float base = (g < 2) ? cosf(ang) : sinf(ang);
            float v = pr * base;
            if ((g & 1) && (i & 1)) v = -v;
            vals[i] = v; n2 += v * v; pr *= rr;
        }
        float G  = (n2 == 0.0f) ? 6.0f : sqrtf(n2);
        float gi = 1.0f / G;
        for (int i = 0; i < T_DIM; ++i) g_Dmat[i * KDIM + j] = vals[i] * gi;
    }
    __syncthreads();

    // 2. ||DtD||_F^2 without storing DtD
    float sq = 0.0f;
    for (int e = tid; e < KDIM * KDIM; e += 1024) {
        int i = e / KDIM, jj = e % KDIM;
        float s = 0.0f;
        for (int t = 0; t < T_DIM; ++t)
            s += g_Dmat[t * KDIM + i] * g_Dmat[t * KDIM + jj];
        sq += s * s;
    }
    float ws = warp_sum(sq);
    if ((tid & 31) == 0) rbuf[tid >> 5] = ws;
    __syncthreads();
    if (tid == 0) {
        float tot = 0.0f;
        for (int i = 0; i < 32; ++i) tot += rbuf[i];
        float L = sqrtf(tot);
        float linv = 1.0f / L;
        g_linv  = linv;
        g_lambd = LAM_C * linv;
        double t = 1.0;
        for (int k = 0; k < MAXIT; ++k) {
            double tn = (1.0 + sqrt(1.0 + 4.0 * t * t)) * 0.5;
            g_tts[k] = (float)((t - 1.0) / tn);
            t = tn;
        }
        g_count = 0;
        g_gen   = 0;
    }
    if (tid < NCTA) g_part[tid] = 0.0f;
}

// ---------------- persistent FISTA kernel (factorized, mma.sync bf16) ------
// Iteration: z = D48 @ y  (stage1)  ->  acc = DtY - linv*D^T @ z  (stage2)
//            v = acc + y ; shrink ; momentum.
__global__ void __launch_bounds__(NTHREADS, 1)
fista_kernel(const float* __restrict__ x_in, float* __restrict__ out) {
    extern __shared__ __align__(16) char smem[];
    float* red    = (float*)(smem + RED_OFF);
    int*   s_stop = (int*)(smem + STOP_OFF);
    float* tts_s  = (float*)(smem + TTS_OFF);

    const int tid = threadIdx.x;
    const int wid = tid >> 5;
    const int l   = tid & 31;
    const int wm  = wid >> 2;          // stage2: 0..1 (80-row half)
    const int wn  = wid & 3;           // stage2: 0..3 (16-col stripe)
    const int g   = l >> 2;            // groupID
    const int i4  = l & 3;             // threadID_in_group
    const int cta = blockIdx.x;
    const int b   = cta >> 6;
    const int p0  = (cta & 63) * PCOLS;

    const float linv  = g_linv;
    const float lambd = g_lambd;

    // ---- stage dict [36][160] and x tile [36][64] fp32; copy tts ----
    for (int e = tid; e < T_DIM * KDIM; e += NTHREADS)
        *(float*)(smem + DICT_STAGE + e * 4) = g_Dmat[e];
    for (int e = tid; e < T_DIM * PCOLS; e += NTHREADS) {
        int t = e >> 6, pp = e & 63;
        *(float*)(smem + X_STAGE + e * 4) = x_in[(b * T_DIM + t) * PDIM + p0 + pp];
    }
    if (tid < MAXIT) tts_s[tid] = g_tts[tid];
    __syncthreads();

    // ---- DtY = linv * D^T x -> registers (c-frag order), kept in regs ----
    float dty[40];
    {
        #pragma unroll
        for (int v = 0; v < 40; ++v) dty[v] = 0.0f;
        const float* Ds = (const float*)(smem + DICT_STAGE);
        const float* Xs = (const float*)(smem + X_STAGE);
        for (int t = 0; t < T_DIM; ++t) {
            float dr[10], xc[4];
            #pragma unroll
            for (int mt = 0; mt < 5; ++mt) {
                dr[mt * 2]     = Ds[t * KDIM + wm * 80 + mt * 16 + g];
                dr[mt * 2 + 1] = Ds[t * KDIM + wm * 80 + mt * 16 + g + 8];
            }
            #pragma unroll
            for (int nt = 0; nt < 2; ++nt) {
                xc[nt * 2]     = Xs[t * PCOLS + wn * 16 + nt * 8 + i4 * 2];
                xc[nt * 2 + 1] = Xs[t * PCOLS + wn * 16 + nt * 8 + i4 * 2 + 1];
            }
            #pragma unroll
            for (int mt = 0; mt < 5; ++mt)
                #pragma unroll
                for (int nt = 0; nt < 2; ++nt)
                    #pragma unroll
                    for (int q = 0; q < 4; ++q)
                        dty[(mt * 2 + nt) * 4 + q] =
                            fmaf(dr[mt * 2 + (q >> 1)], xc[nt * 2 + (q & 1)],
                                 dty[(mt * 2 + nt) * 4 + q]);
        }
        #pragma unroll
        for (int v = 0; v < 40; ++v) dty[v] *= linv;
    }
    __syncthreads();   // dict/x staging consumed

    // ---- pack stage-1 operand: D48[48,160] (rows>=36 zero), frag f1 = mt*10+ks
    for (int e = tid; e < 30 * 32 * 4; e += NTHREADS) {
        int frag = e >> 7;
        int lane = (e >> 2) & 31;
        int reg  = e & 3;
        int mt   = frag / 10, ks = frag % 10;
        int r = mt * 16 + (lane >> 2) + ((reg & 1) ? 8 : 0);
        int k = ks * 16 + (lane & 3) * 2 + ((reg & 2) ? 8 : 0);
        float v0 = (r < T_DIM) ? g_Dmat[r * KDIM + k] : 0.0f;
        float v1 = (r < T_DIM) ? g_Dmat[r * KDIM + k + 1] : 0.0f;
        uint32_t hi, lo;
        split_pack(v0, v1, hi, lo);
        *(uint32_t*)(smem + A1H_OFF + e * 4) = hi;
        *(uint32_t*)(smem + A1L_OFF + e * 4) = lo;
    }
    // ---- pack stage-2 operand: (-linv)*D^T [160,48] (cols>=36 zero), f2 = mt*3+ks
    for (int e = tid; e < 30 * 32 * 4; e += NTHREADS) {
        int frag = e >> 7;
        int lane = (e >> 2) & 31;
        int reg  = e & 3;
        int mt   = frag / 3, ks = frag % 3;
        int r = mt * 16 + (lane >> 2) + ((reg & 1) ? 8 : 0);
        int k = ks * 16 + (lane & 3) * 2 + ((reg & 2) ? 8 : 0);
        float v0 = (k < T_DIM) ? -linv * g_Dmat[k * KDIM + r] : 0.0f;
        float v1 = (k + 1 < T_DIM) ? -linv * g_Dmat[(k + 1) * KDIM + r] : 0.0f;
        uint32_t hi, lo;
        split_pack(v0, v1, hi, lo);
        *(uint32_t*)(smem + A2H_OFF + e * 4) = hi;
        *(uint32_t*)(smem + A2L_OFF + e * 4) = lo;
    }
    // ---- zero y (fp32) ----
    for (int e = tid; e < PCOLS * YSTR; e += NTHREADS)
        *(float*)(smem + Y_OFF + e * 4) = 0.0f;

    float xold[40];
    #pragma unroll
    for (int v = 0; v < 40; ++v) xold[v] = 0.0f;
    __syncthreads();

    const float* Yp = (const float*)(smem + Y_OFF);
    const float* Zp = (const float*)(smem + Z_OFF);
    float*       Zw = (float*)(smem + Z_OFF);

    // ---- main FISTA loop ----
    for (int it = 0; it < MAXIT; ++it) {
        // ===== stage 1: z[48,64] = D48 @ y ; warp covers n-stripe wid*8 =====
        float z1[3][4];
        #pragma unroll
        for (int mt = 0; mt < 3; ++mt)
            #pragma unroll
            for (int q = 0; q < 4; ++q) z1[mt][q] = 0.0f;

        #pragma unroll 2
        for (int ks = 0; ks < 10; ++ks) {
            const float* yrow = Yp + (wid * 8 + g) * YSTR + ks * 16 + i4 * 2;
            float2 v0 = *(const float2*)(yrow);
            float2 v1 = *(const float2*)(yrow + 8);
            uint32_t bh[2], bl[2];
            split_pack(v0.x, v0.y, bh[0], bl[0]);
            split_pack(v1.x, v1.y, bh[1], bl[1]);
            uint32_t a1h[3][4], a1l[3][4];
            #pragma unroll
            for (int mt = 0; mt < 3; ++mt) {
                int fi = (mt * 10 + ks) * 32 + l;
                uint4 Ah = *(const uint4*)(smem + A1H_OFF + fi * 16);
                uint4 Al = *(const uint4*)(smem + A1L_OFF + fi * 16);
                a1h[mt][0] = Ah.x; a1h[mt][1] = Ah.y; a1h[mt][2] = Ah.z; a1h[mt][3] = Ah.w;
                a1l[mt][0] = Al.x; a1l[mt][1] = Al.y; a1l[mt][2] = Al.z; a1l[mt][3] = Al.w;
            }
            #pragma unroll
            for (int mt = 0; mt < 3; ++mt) mma_bf16(z1[mt], a1h[mt], bh);
            #pragma unroll
            for (int mt = 0; mt < 3; ++mt) mma_bf16(z1[mt], a1h[mt], bl);
            #pragma unroll
            for (int mt = 0; mt < 3; ++mt) mma_bf16(z1[mt], a1l[mt], bh);
        }
        // write z to smem (conflict-free: bank = 8*i4 + g + const)
        #pragma unroll
        for (int mt = 0; mt < 3; ++mt)
            #pragma unroll
            for (int q = 0; q < 4; ++q) {
                int row = mt * 16 + g + ((q >> 1) << 3);
                int col = wid * 8 + i4 * 2 + (q & 1);
                Zw[col * ZSTR + row] = z1[mt][q];
            }

        // join the gen-poll (partials of it-1 globally visible after this)
        if (it > 0 && tid == 0) {
            while (*((volatile unsigned*)&g_gen) < (unsigned)it) { __nanosleep(32); }
        }
        __syncthreads();   // sync_Z: z written; y reads done; poll joined

        // stop decision for it-1, overlapped with stage 2 (w0 only)
        if (it > 0 && wid == 0) {
            float s = *((volatile float*)(g_part + l));
            s += *((volatile float*)(g_part + l + 32));
            s += *((volatile float*)(g_part + l + 64));
            s += *((volatile float*)(g_part + l + 96));
            float tot = warp_sum(s);
            if (l == 0) {
                float denom = (it == 1) ? (float)PDIM : (float)KDIM;
                *s_stop = (sqrtf(tot) < TOL_C * denom) ? 1 : 0;
            }
        }

        // ===== stage 2: acc = dty + (-linv*D^T) @ z ; warp grid 2x4 =====
        float acc[10][4];
        #pragma unroll
        for (int mt = 0; mt < 5; ++mt)
            #pragma unroll
            for (int nt = 0; nt < 2; ++nt)
                #pragma unroll
                for (int q = 0; q < 4; ++q)
                    acc[mt * 2 + nt][q] = dty[(mt * 2 + nt) * 4 + q];

        #pragma unroll
        for (int ks = 0; ks < 3; ++ks) {
            uint32_t bh[2][2], bl[2][2];
            #pragma unroll
            for (int nt = 0; nt < 2; ++nt) {
                const float* zrow = Zp + (wn * 16 + nt * 8 + g) * ZSTR + ks * 16 + i4 * 2;
                float2 v0 = *(const float2*)(zrow);
                float2 v1 = *(const float2*)(zrow + 8);
                split_pack(v0.x, v0.y, bh[nt][0], bl[nt][0]);
                split_pack(v1.x, v1.y, bh[nt][1], bl[nt][1]);
            }
            uint32_t ah[5][4], al[5][4];
            #pragma unroll
            for (int mt = 0; mt < 5; ++mt) {
                int fi = ((wm * 5 + mt) * 3 + ks) * 32 + l;
                uint4 Ah = *(const uint4*)(smem + A2H_OFF + fi * 16);
                uint4 Al = *(const uint4*)(smem + A2L_OFF + fi * 16);
                ah[mt][0] = Ah.x; ah[mt][1] = Ah.y; ah[mt][2] = Ah.z; ah[mt][3] = Ah.w;
                al[mt][0] = Al.x; al[mt][1] = Al.y; al[mt][2] = Al.z; al[mt][3] = Al.w;
            }
            #pragma unroll
            for (int mt = 0; mt < 5; ++mt)
                #pragma unroll
                for (int nt = 0; nt < 2; ++nt)
                    mma_bf16(acc[mt * 2 + nt], ah[mt], bh[nt]);
            #pragma unroll
            for (int mt = 0; mt < 5; ++mt)
                #pragma unroll
                for (int nt = 0; nt < 2; ++nt)
                    mma_bf16(acc[mt * 2 + nt], ah[mt], bl[nt]);
            #pragma unroll
            for (int mt = 0; mt < 5; ++mt)
                #pragma unroll
                for (int nt = 0; nt < 2; ++nt)
                    mma_bf16(acc[mt * 2 + nt], al[mt], bh[nt]);
        }

        const float tt = tts_s[it];
        float dsum = 0.0f;

        // epilogue (speculative): v = acc + y_old ; shrink ; momentum ; write y
        #pragma unroll
        for (int mt = 0; mt < 5; ++mt)
            #pragma unroll
            for (int nt = 0; nt < 2; ++nt)
                #pragma unroll
                for (int q = 0; q < 4; ++q) {
                    int ix  = (mt * 2 + nt) * 4 + q;
                    int row = wm * 80 + mt * 16 + g + ((q >> 1) << 3);
                    int col = wn * 16 + nt * 8 + i4 * 2 + (q & 1);
                    float yo_v = Yp[col * YSTR + row];          // y (exact fp32 term)
                    float v  = acc[mt * 2 + nt][q] + yo_v;
                    float a  = fabsf(v) - lambd;
                    float xn = (a > 0.0f) ? copysignf(a, v) : 0.0f;
                    float xo = xold[ix];
                    float d  = xn - xo;
                    dsum = fmaf(d, d, dsum);
                    float yn = fmaf(tt, d, xn);
                    xold[ix] = xn;
                    *(float*)(smem + Y_OFF + (col * YSTR + row) * 4) = yn;
                }

        float ws = warp_sum(dsum);
        if (l == 0) red[wid] = ws;
        __syncthreads();   // sync_B: y + red + s_stop visible

        if (it > 0 && *s_stop) {
            // rollback speculative epilogue: xo = xn - (y - xn)/tt  (tt>0 for it>=1)
            float inv_tt = 1.0f / tt;
            #pragma unroll
            for (int mt = 0; mt < 5; ++mt)
                #pragma unroll
                for (int nt = 0; nt < 2; ++nt)
                    #pragma unroll
                    for (int q = 0; q < 4; ++q) {
                        int ix  = (mt * 2 + nt) * 4 + q;
                        int row = wm * 80 + mt * 16 + g + ((q >> 1) << 3);
                        int col = wn * 16 + nt * 8 + i4 * 2 + (q & 1);
                        float yv = Yp[col * YSTR + row];
                        float xn = xold[ix];
                        xold[ix] = xn - (yv - xn) * inv_tt;
                    }
            break;
        }

        // publish partial + arrive (no wait; decision deferred)
        if (tid == 0) {
            float s = red[0];
            #pragma unroll
            for (int i = 1; i < 8; ++i) s += red[i];
            g_part[cta] = s;
            __threadfence();
            unsigned tk = atomicAdd(&g_count, 1);
            if (tk == (unsigned)(NCTA - 1)) {
                g_count = 0;
                __threadfence();
                atomicAdd(&g_gen, 1);
            }
        }
    }

    // ---- output: out[(b*160 + row)*4096 + p0 + col] ----
    #pragma unroll
    for (int mt = 0; mt < 5; ++mt)
        #pragma unroll
        for (int nt = 0; nt < 2; ++nt)
            #pragma unroll
            for (int q = 0; q < 4; ++q) {
                int row = wm * 80 + mt * 16 + g + ((q >> 1) << 3);
                int col = wn * 16 + nt * 8 + i4 * 2 + (q & 1);
                out[((size_t)b * KDIM + row) * PDIM + p0 + col] =
                    xold[(mt * 2 + nt) * 4 + q];
            }
}

// ---------------- launch ----------------
extern "C" void kernel_launch(void* const* d_in, const int* in_sizes, int n_in,
                              void* d_out, int out_size) {
    const float* Drr    = (const float*)d_in[0];
    const float* Dtheta = (const float*)d_in[1];
    const float* x      = (const float*)d_in[2];
    float* out = (float*)d_out;

    cudaFuncSetAttribute(fista_kernel, cudaFuncAttributeMaxDynamicSharedMemorySize, SMEM_TOTAL);
    setup_kernel<<<1, 1024>>>(Drr, Dtheta);
    fista_kernel<<<NCTA, NTHREADS, SMEM_TOTAL>>>(x, out);
}